// round 7
// baseline (speedup 1.0000x reference)
#include <cuda_runtime.h>
#include <cuda_fp16.h>

// SimpleRNN: 2-layer tanh RNN, B=8192, S=512, H=16, INPUT=1, fc on last step.
// R6: fp16 hidden-state exchange (halves smem crossbar bytes, the measured
// bottleneck). Interleaved f16x2 layout: word 2k = h0 pair k, word 2k+1 = h1
// pair k -> one STS.64 store, 4 LDS.128 reads per thread-step. Unroll x2 with
// static parity buffers, float2 x loads, peeled epilogue. Weights register-
// resident f32x2; math in f32 via fma.rn.f32x2; tanh via MUFU.

#define BATCH   8192
#define SEQ     512
#define HID     16
#define NB      32        // batches per block
#define THREADS 256       // 8 lanes per batch
#define WROW    20        // u32 words per batch row (16 data + 4 pad)

typedef unsigned long long u64;
typedef unsigned int u32;

__device__ __forceinline__ u64 fma2(u64 a, u64 b, u64 c) {
    u64 d;
    asm("fma.rn.f32x2 %0, %1, %2, %3;" : "=l"(d) : "l"(a), "l"(b), "l"(c));
    return d;
}
__device__ __forceinline__ u64 pack2(float lo, float hi) {
    u64 d;
    asm("mov.b64 %0, {%1, %2};" : "=l"(d) : "f"(lo), "f"(hi));
    return d;
}
__device__ __forceinline__ void unpack2(u64 v, float& lo, float& hi) {
    asm("mov.b64 {%0, %1}, %2;" : "=f"(lo), "=f"(hi) : "l"(v));
}
__device__ __forceinline__ float tanh_mufu(float v) {
    float r;
    asm("tanh.approx.f32 %0, %1;" : "=f"(r) : "f"(v));
    return r;
}
__device__ __forceinline__ u64 h2_to_f32x2(u32 w) {
    __half2 h = *reinterpret_cast<const __half2*>(&w);
    float2 f = __half22float2(h);
    return pack2(f.x, f.y);
}

__global__ __launch_bounds__(THREADS, 2)
void rnn2_kernel(const float* __restrict__ x,
                 const float* __restrict__ Wih0, const float* __restrict__ Whh0,
                 const float* __restrict__ bih0, const float* __restrict__ bhh0,
                 const float* __restrict__ Wih1, const float* __restrict__ Whh1,
                 const float* __restrict__ bih1, const float* __restrict__ bhh1,
                 const float* __restrict__ Wfc,  const float* __restrict__ bfc,
                 float* __restrict__ out)
{
    // double-buffered fp16 hidden state, interleaved:
    // word 2k = h0 pair k (f16x2), word 2k+1 = h1 pair k.
    __shared__ u32 hbuf[2][NB][WROW];

    const int tid = threadIdx.x;
    const int lb  = tid >> 3;          // local batch 0..31
    const int k   = tid & 7;           // row-pair owner 0..7
    const int b   = blockIdx.x * NB + lb;
    const int ra  = 2 * k, rb = 2 * k + 1;

    // ---- all weights to registers (packed f32x2 along j) ----
    u64 whh0a[8], whh0b[8], wih1a[8], wih1b[8], whh1a[8], whh1b[8];
#pragma unroll
    for (int j = 0; j < 8; j++) {
        whh0a[j] = *(const u64*)(Whh0 + ra * HID + 2 * j);
        whh0b[j] = *(const u64*)(Whh0 + rb * HID + 2 * j);
        wih1a[j] = *(const u64*)(Wih1 + ra * HID + 2 * j);
        wih1b[j] = *(const u64*)(Wih1 + rb * HID + 2 * j);
        whh1a[j] = *(const u64*)(Whh1 + ra * HID + 2 * j);
        whh1b[j] = *(const u64*)(Whh1 + rb * HID + 2 * j);
    }
    const float wia = Wih0[ra], wib = Wih0[rb];
    const float c0a = bih0[ra] + bhh0[ra], c0b = bih0[rb] + bhh0[rb];
    const float c1a = bih1[ra] + bhh1[ra], c1b = bih1[rb] + bhh1[rb];

    u32* row0 = &hbuf[0][lb][0];
    u32* row1 = &hbuf[1][lb][0];

    // zero parity-0 state (f16x2 zero == bit pattern 0)
    *(uint2*)(row0 + 2 * k) = make_uint2(0u, 0u);
    __syncwarp();

    const float* xb = x + (size_t)b * SEQ;
    float2 xc = *(const float2*)xb;

    // one sub-step: reads src (h0(t-1), h1(t-2)), computes h0(t), h1(t-1),
    // stores to dst. zero_h1 forces stored h1 to the initial state at t=0.
    auto substep = [&](const u32* src, u32* dst, float xv, bool zero_h1) {
        u64 a0 = pack2(fmaf(wia, xv, c0a), 0.f);
        u64 b0 = pack2(fmaf(wib, xv, c0b), 0.f);
        u64 a1 = pack2(c1a, 0.f);
        u64 b1 = pack2(c1b, 0.f);
#pragma unroll
        for (int g = 0; g < 4; g++) {
            uint4 q = ((const uint4*)src)[g];
            u64 h0p0 = h2_to_f32x2(q.x);   // h0 pair 2g
            u64 h1p0 = h2_to_f32x2(q.y);   // h1 pair 2g
            u64 h0p1 = h2_to_f32x2(q.z);   // h0 pair 2g+1
            u64 h1p1 = h2_to_f32x2(q.w);   // h1 pair 2g+1
            a0 = fma2(whh0a[2 * g],     h0p0, a0);
            b0 = fma2(whh0b[2 * g],     h0p0, b0);
            a1 = fma2(wih1a[2 * g],     h0p0, a1);
            b1 = fma2(wih1b[2 * g],     h0p0, b1);
            a1 = fma2(whh1a[2 * g],     h1p0, a1);
            b1 = fma2(whh1b[2 * g],     h1p0, b1);
            a0 = fma2(whh0a[2 * g + 1], h0p1, a0);
            b0 = fma2(whh0b[2 * g + 1], h0p1, b0);
            a1 = fma2(wih1a[2 * g + 1], h0p1, a1);
            b1 = fma2(wih1b[2 * g + 1], h0p1, b1);
            a1 = fma2(whh1a[2 * g + 1], h1p1, a1);
            b1 = fma2(whh1b[2 * g + 1], h1p1, b1);
        }
        float la, ha, lc, hc;
        unpack2(a0, la, ha);
        unpack2(b0, lc, hc);
        float h0a = tanh_mufu(la + ha);
        float h0b = tanh_mufu(lc + hc);
        unpack2(a1, la, ha);
        unpack2(b1, lc, hc);
        float h1a = tanh_mufu(la + ha);
        float h1b = tanh_mufu(lc + hc);
        if (zero_h1) { h1a = 0.f; h1b = 0.f; }   // h1(-1) = 0

        __half2 w0 = __floats2half2_rn(h0a, h0b);
        __half2 w1 = __floats2half2_rn(h1a, h1b);
        uint2 st;
        st.x = *reinterpret_cast<const u32*>(&w0);
        st.y = *reinterpret_cast<const u32*>(&w1);
        *(uint2*)(dst + 2 * k) = st;
    };

#pragma unroll 1
    for (int t = 0; t < SEQ; t += 2) {
        int tn = (t + 2 < SEQ) ? t + 2 : (SEQ - 2);
        float2 xn = *(const float2*)(xb + tn);

        substep(row0, row1, xc.x, t == 0);
        __syncwarp();
        substep(row1, row0, xc.y, false);
        __syncwarp();

        xc = xn;
    }

    // ---- epilogue: h1(SEQ-1) from row0 (h0(511), h1(510)) ----
    float h1a, h1b;
    {
        u64 a1 = pack2(c1a, 0.f);
        u64 b1 = pack2(c1b, 0.f);
#pragma unroll
        for (int g = 0; g < 4; g++) {
            uint4 q = ((const uint4*)row0)[g];
            u64 h0p0 = h2_to_f32x2(q.x);
            u64 h1p0 = h2_to_f32x2(q.y);
            u64 h0p1 = h2_to_f32x2(q.z);
            u64 h1p1 = h2_to_f32x2(q.w);
            a1 = fma2(wih1a[2 * g],     h0p0, a1);
            b1 = fma2(wih1b[2 * g],     h0p0, b1);
            a1 = fma2(whh1a[2 * g],     h1p0, a1);
            b1 = fma2(whh1b[2 * g],     h1p0, b1);
            a1 = fma2(wih1a[2 * g + 1], h0p1, a1);
            b1 = fma2(wih1b[2 * g + 1], h0p1, b1);
            a1 = fma2(whh1a[2 * g + 1], h1p1, a1);
            b1 = fma2(whh1b[2 * g + 1], h1p1, b1);
        }
        float la, ha, lc, hc;
        unpack2(a1, la, ha);
        unpack2(b1, lc, hc);
        h1a = tanh_mufu(la + ha);
        h1b = tanh_mufu(lc + hc);
    }

    // ---- fc: partial over own 2 rows, reduce across 8 lanes ----
    float p = fmaf(Wfc[ra], h1a, Wfc[rb] * h1b);
    p += __shfl_down_sync(0xffffffffu, p, 4, 8);
    p += __shfl_down_sync(0xffffffffu, p, 2, 8);
    p += __shfl_down_sync(0xffffffffu, p, 1, 8);
    if (k == 0) out[b] = p + bfc[0];
}

extern "C" void kernel_launch(void* const* d_in, const int* in_sizes, int n_in,
                              void* d_out, int out_size)
{
    const float* x    = (const float*)d_in[0];
    const float* Wih0 = (const float*)d_in[1];
    const float* Whh0 = (const float*)d_in[2];
    const float* bih0 = (const float*)d_in[3];
    const float* bhh0 = (const float*)d_in[4];
    const float* Wih1 = (const float*)d_in[5];
    const float* Whh1 = (const float*)d_in[6];
    const float* bih1 = (const float*)d_in[7];
    const float* bhh1 = (const float*)d_in[8];
    const float* Wfc  = (const float*)d_in[9];
    const float* bfc  = (const float*)d_in[10];
    float* out = (float*)d_out;

    rnn2_kernel<<<BATCH / NB, THREADS>>>(x, Wih0, Whh0, bih0, bhh0,
                                         Wih1, Whh1, bih1, bhh1,
                                         Wfc, bfc, out);
}

// round 9
// speedup vs baseline: 1.1811x; 1.1811x over previous
#include <cuda_runtime.h>

// SimpleRNN: 2-layer tanh RNN, B=8192, S=512, H=16, INPUT=1, fc on last step.
// R7: dual-batch streams per thread. Each thread owns row-pair k of TWO
// batches -> two fully independent dependence chains per warp sharing one
// register-resident weight set (96 regs). f32 smem exchange (no conversions),
// interleaved quad layout (h0 pair + h1 pair per 16B) -> 8 LDS.128 reads and
// ONE STS.128 store per stream per step. Layer-1 lagged one step (R5 scheme),
// one syncwarp per substep, MUFU tanh.

#define BATCH   8192
#define SEQ     512
#define HID     16
#define LPB     8         // lanes per batch
#define THREADS 128       // 16 lane-groups
#define BPB     32        // batches per block (16 groups x 2 streams)
#define HROW    36        // f32 per batch row: 8 quads (32) + 4 pad

typedef unsigned long long u64;

__device__ __forceinline__ u64 fma2(u64 a, u64 b, u64 c) {
    u64 d;
    asm("fma.rn.f32x2 %0, %1, %2, %3;" : "=l"(d) : "l"(a), "l"(b), "l"(c));
    return d;
}
__device__ __forceinline__ u64 pack2(float lo, float hi) {
    u64 d;
    asm("mov.b64 %0, {%1, %2};" : "=l"(d) : "f"(lo), "f"(hi));
    return d;
}
__device__ __forceinline__ void unpack2(u64 v, float& lo, float& hi) {
    asm("mov.b64 {%0, %1}, %2;" : "=f"(lo), "=f"(hi) : "l"(v));
}
__device__ __forceinline__ float tanh_mufu(float v) {
    float r;
    asm("tanh.approx.f32 %0, %1;" : "=f"(r) : "f"(v));
    return r;
}

__global__ __launch_bounds__(THREADS, 2)
void rnn2_kernel(const float* __restrict__ x,
                 const float* __restrict__ Wih0, const float* __restrict__ Whh0,
                 const float* __restrict__ bih0, const float* __restrict__ bhh0,
                 const float* __restrict__ Wih1, const float* __restrict__ Whh1,
                 const float* __restrict__ bih1, const float* __restrict__ bhh1,
                 const float* __restrict__ Wfc,  const float* __restrict__ bfc,
                 float* __restrict__ out)
{
    // double-buffered interleaved state: quad q = {h0[2q],h0[2q+1],h1[2q],h1[2q+1]}
    __shared__ __align__(16) float hbuf[2][BPB][HROW];

    const int tid = threadIdx.x;
    const int g   = tid >> 3;          // lane-group 0..15
    const int k   = tid & 7;           // row-pair owner 0..7
    const int rA  = 2 * g;             // smem row, stream A
    const int rB  = 2 * g + 1;         // smem row, stream B
    const int bA  = blockIdx.x * BPB + rA;
    const int bB  = bA + 1;
    const int ra  = 2 * k, rb = 2 * k + 1;

    // ---- all weights to registers (packed f32x2 along j), shared by streams ----
    u64 whh0a[8], whh0b[8], wih1a[8], wih1b[8], whh1a[8], whh1b[8];
#pragma unroll
    for (int j = 0; j < 8; j++) {
        whh0a[j] = *(const u64*)(Whh0 + ra * HID + 2 * j);
        whh0b[j] = *(const u64*)(Whh0 + rb * HID + 2 * j);
        wih1a[j] = *(const u64*)(Wih1 + ra * HID + 2 * j);
        wih1b[j] = *(const u64*)(Wih1 + rb * HID + 2 * j);
        whh1a[j] = *(const u64*)(Whh1 + ra * HID + 2 * j);
        whh1b[j] = *(const u64*)(Whh1 + rb * HID + 2 * j);
    }
    const float wia = Wih0[ra], wib = Wih0[rb];
    const float c0a = bih0[ra] + bhh0[ra], c0b = bih0[rb] + bhh0[rb];
    const float c1a = bih1[ra] + bhh1[ra], c1b = bih1[rb] + bhh1[rb];

    float* r0A = &hbuf[0][rA][0];
    float* r0B = &hbuf[0][rB][0];
    float* r1A = &hbuf[1][rA][0];
    float* r1B = &hbuf[1][rB][0];

    // zero parity-0 state (quad k of both rows)
    {
        ulonglong2 z; z.x = 0ull; z.y = 0ull;
        ((ulonglong2*)r0A)[k] = z;
        ((ulonglong2*)r0B)[k] = z;
    }
    __syncwarp();

    const float* xbA = x + (size_t)bA * SEQ;
    const float* xbB = x + (size_t)bB * SEQ;

    float h1aA = 0.f, h1bA = 0.f, h1aB = 0.f, h1bB = 0.f;

    // one sub-step over both streams: reads src (h0(t-1), h1(t-2)), computes
    // h0(t), h1(t-1), stores to dst. zero_h1 forces h1(-1)=0 at t=0.
    auto substep = [&](const float* srcA, const float* srcB,
                       float* dstA, float* dstB,
                       float xA, float xB, bool zero_h1) {
        u64 a0A = pack2(fmaf(wia, xA, c0a), 0.f);
        u64 b0A = pack2(fmaf(wib, xA, c0b), 0.f);
        u64 a1A = pack2(c1a, 0.f);
        u64 b1A = pack2(c1b, 0.f);
        u64 a0B = pack2(fmaf(wia, xB, c0a), 0.f);
        u64 b0B = pack2(fmaf(wib, xB, c0b), 0.f);
        u64 a1B = pack2(c1a, 0.f);
        u64 b1B = pack2(c1b, 0.f);
#pragma unroll
        for (int q = 0; q < 8; q++) {
            ulonglong2 qa = ((const ulonglong2*)srcA)[q];  // .x=h0 pair, .y=h1 pair
            ulonglong2 qb = ((const ulonglong2*)srcB)[q];
            a0A = fma2(whh0a[q], qa.x, a0A);
            b0A = fma2(whh0b[q], qa.x, b0A);
            a0B = fma2(whh0a[q], qb.x, a0B);
            b0B = fma2(whh0b[q], qb.x, b0B);
            a1A = fma2(wih1a[q], qa.x, a1A);
            b1A = fma2(wih1b[q], qa.x, b1A);
            a1B = fma2(wih1a[q], qb.x, a1B);
            b1B = fma2(wih1b[q], qb.x, b1B);
            a1A = fma2(whh1a[q], qa.y, a1A);
            b1A = fma2(whh1b[q], qa.y, b1A);
            a1B = fma2(whh1a[q], qb.y, a1B);
            b1B = fma2(whh1b[q], qb.y, b1B);
        }
        float la, ha, lc, hc;
        unpack2(a0A, la, ha);
        unpack2(b0A, lc, hc);
        float h0aA = tanh_mufu(la + ha);
        float h0bA = tanh_mufu(lc + hc);
        unpack2(a1A, la, ha);
        unpack2(b1A, lc, hc);
        h1aA = tanh_mufu(la + ha);
        h1bA = tanh_mufu(lc + hc);
        unpack2(a0B, la, ha);
        unpack2(b0B, lc, hc);
        float h0aB = tanh_mufu(la + ha);
        float h0bB = tanh_mufu(lc + hc);
        unpack2(a1B, la, ha);
        unpack2(b1B, lc, hc);
        h1aB = tanh_mufu(la + ha);
        h1bB = tanh_mufu(lc + hc);
        if (zero_h1) { h1aA = h1bA = h1aB = h1bB = 0.f; }

        ulonglong2 stA, stB;
        stA.x = pack2(h0aA, h0bA);
        stA.y = pack2(h1aA, h1bA);
        stB.x = pack2(h0aB, h0bB);
        stB.y = pack2(h1aB, h1bB);
        ((ulonglong2*)dstA)[k] = stA;
        ((ulonglong2*)dstB)[k] = stB;
    };

    float2 xA = *(const float2*)xbA;
    float2 xB = *(const float2*)xbB;

#pragma unroll 1
    for (int tt = 0; tt < SEQ / 2; tt++) {
        int tn = (2 * tt + 2 < SEQ) ? 2 * tt + 2 : (SEQ - 2);
        float2 xAn = *(const float2*)(xbA + tn);
        float2 xBn = *(const float2*)(xbB + tn);

        substep(r0A, r0B, r1A, r1B, xA.x, xB.x, tt == 0);
        __syncwarp();
        substep(r1A, r1B, r0A, r0B, xA.y, xB.y, false);
        __syncwarp();

        xA = xAn;
        xB = xBn;
    }

    // peel final sub-step: computes h1(SEQ-1) (h0(SEQ) discarded); x value
    // only feeds the discarded h0, any finite value is fine.
    substep(r0A, r0B, r1A, r1B, xA.x, xB.x, false);

    // ---- fc on h1(SEQ-1): partial over own 2 rows, reduce across 8 lanes ----
    const float wfa = Wfc[ra], wfb = Wfc[rb], bf0 = bfc[0];
    float pA = fmaf(wfa, h1aA, wfb * h1bA);
    float pB = fmaf(wfa, h1aB, wfb * h1bB);
    pA += __shfl_down_sync(0xffffffffu, pA, 4, 8);
    pB += __shfl_down_sync(0xffffffffu, pB, 4, 8);
    pA += __shfl_down_sync(0xffffffffu, pA, 2, 8);
    pB += __shfl_down_sync(0xffffffffu, pB, 2, 8);
    pA += __shfl_down_sync(0xffffffffu, pA, 1, 8);
    pB += __shfl_down_sync(0xffffffffu, pB, 1, 8);
    if (k == 0) {
        out[bA] = pA + bf0;
        out[bB] = pB + bf0;
    }
}

extern "C" void kernel_launch(void* const* d_in, const int* in_sizes, int n_in,
                              void* d_out, int out_size)
{
    const float* x    = (const float*)d_in[0];
    const float* Wih0 = (const float*)d_in[1];
    const float* Whh0 = (const float*)d_in[2];
    const float* bih0 = (const float*)d_in[3];
    const float* bhh0 = (const float*)d_in[4];
    const float* Wih1 = (const float*)d_in[5];
    const float* Whh1 = (const float*)d_in[6];
    const float* bih1 = (const float*)d_in[7];
    const float* bhh1 = (const float*)d_in[8];
    const float* Wfc  = (const float*)d_in[9];
    const float* bfc  = (const float*)d_in[10];
    float* out = (float*)d_out;

    rnn2_kernel<<<BATCH / BPB, THREADS>>>(x, Wih0, Whh0, bih0, bhh0,
                                          Wih1, Whh1, bih1, bhh1,
                                          Wfc, bfc, out);
}

// round 11
// speedup vs baseline: 1.2171x; 1.0305x over previous
#include <cuda_runtime.h>

// SimpleRNN: 2-layer tanh RNN, B=8192, S=512, H=16, INPUT=1, fc on last step.
// R9: 1-warp blocks (32 thr, 8 batches, grid 1024) for load balance + phase
// drift; split layer-1 accumulation into two 8-deep fma2 chains merged with
// add.f32x2; h0-tanh MUFUs emitted between the wih1 and whh1 fma blocks so
// the MUFU burst overlaps fma issue. Dual-batch streams per thread, weights
// register-resident f32x2, f32 smem exchange, lagged layer-1, MUFU tanh.

#define BATCH   8192
#define SEQ     512
#define HID     16
#define THREADS 32        // one warp per block: 4 groups x 8 lanes
#define BPB     8         // batches per block (4 groups x 2 streams)
#define HROW    36        // f32 per batch row: 8 quads (32) + 4 pad

typedef unsigned long long u64;

__device__ __forceinline__ u64 fma2(u64 a, u64 b, u64 c) {
    u64 d;
    asm("fma.rn.f32x2 %0, %1, %2, %3;" : "=l"(d) : "l"(a), "l"(b), "l"(c));
    return d;
}
__device__ __forceinline__ u64 add2(u64 a, u64 b) {
    u64 d;
    asm("add.rn.f32x2 %0, %1, %2;" : "=l"(d) : "l"(a), "l"(b));
    return d;
}
__device__ __forceinline__ u64 pack2(float lo, float hi) {
    u64 d;
    asm("mov.b64 %0, {%1, %2};" : "=l"(d) : "f"(lo), "f"(hi));
    return d;
}
__device__ __forceinline__ void unpack2(u64 v, float& lo, float& hi) {
    asm("mov.b64 {%0, %1}, %2;" : "=f"(lo), "=f"(hi) : "l"(v));
}
__device__ __forceinline__ float tanh_mufu(float v) {
    float r;
    asm("tanh.approx.f32 %0, %1;" : "=f"(r) : "f"(v));
    return r;
}

__global__ __launch_bounds__(THREADS)
void rnn2_kernel(const float* __restrict__ x,
                 const float* __restrict__ Wih0, const float* __restrict__ Whh0,
                 const float* __restrict__ bih0, const float* __restrict__ bhh0,
                 const float* __restrict__ Wih1, const float* __restrict__ Whh1,
                 const float* __restrict__ bih1, const float* __restrict__ bhh1,
                 const float* __restrict__ Wfc,  const float* __restrict__ bfc,
                 float* __restrict__ out)
{
    // double-buffered interleaved state: quad q = {h0 pair q, h1 pair q}
    __shared__ __align__(16) float hbuf[2][BPB][HROW];

    const int tid = threadIdx.x;
    const int g   = tid >> 3;          // lane-group 0..3
    const int k   = tid & 7;           // row-pair owner 0..7
    const int rA  = 2 * g;             // smem row, stream A
    const int rB  = 2 * g + 1;         // smem row, stream B
    const int bA  = blockIdx.x * BPB + rA;
    const int bB  = bA + 1;
    const int ra  = 2 * k, rb = 2 * k + 1;

    // ---- all weights to registers (packed f32x2 along j), shared by streams ----
    u64 whh0a[8], whh0b[8], wih1a[8], wih1b[8], whh1a[8], whh1b[8];
#pragma unroll
    for (int j = 0; j < 8; j++) {
        whh0a[j] = *(const u64*)(Whh0 + ra * HID + 2 * j);
        whh0b[j] = *(const u64*)(Whh0 + rb * HID + 2 * j);
        wih1a[j] = *(const u64*)(Wih1 + ra * HID + 2 * j);
        wih1b[j] = *(const u64*)(Wih1 + rb * HID + 2 * j);
        whh1a[j] = *(const u64*)(Whh1 + ra * HID + 2 * j);
        whh1b[j] = *(const u64*)(Whh1 + rb * HID + 2 * j);
    }
    const float wia = Wih0[ra], wib = Wih0[rb];
    const float c0a = bih0[ra] + bhh0[ra], c0b = bih0[rb] + bhh0[rb];
    const float c1a = bih1[ra] + bhh1[ra], c1b = bih1[rb] + bhh1[rb];

    float* r0A = &hbuf[0][rA][0];
    float* r0B = &hbuf[0][rB][0];
    float* r1A = &hbuf[1][rA][0];
    float* r1B = &hbuf[1][rB][0];

    // zero parity-0 state (quad k of both rows)
    {
        ulonglong2 z; z.x = 0ull; z.y = 0ull;
        ((ulonglong2*)r0A)[k] = z;
        ((ulonglong2*)r0B)[k] = z;
    }
    __syncwarp();

    const float* xbA = x + (size_t)bA * SEQ;
    const float* xbB = x + (size_t)bB * SEQ;

    float h1aA = 0.f, h1bA = 0.f, h1aB = 0.f, h1bB = 0.f;

    // one sub-step over both streams: reads src (h0(t-1), h1(t-2)), computes
    // h0(t), h1(t-1), stores to dst. zero_h1 forces h1(-1)=0 at t=0.
    auto substep = [&](const float* srcA, const float* srcB,
                       float* dstA, float* dstB,
                       float xA, float xB, bool zero_h1) {
        u64 a0A = pack2(fmaf(wia, xA, c0a), 0.f);
        u64 b0A = pack2(fmaf(wib, xA, c0b), 0.f);
        u64 a0B = pack2(fmaf(wia, xB, c0a), 0.f);
        u64 b0B = pack2(fmaf(wib, xB, c0b), 0.f);
        u64 a1A = pack2(c1a, 0.f);
        u64 b1A = pack2(c1b, 0.f);
        u64 a1B = pack2(c1a, 0.f);
        u64 b1B = pack2(c1b, 0.f);
        // whh1 partial sums on separate accumulators (8-deep chains)
        u64 c1A_ = 0ull, d1A_ = 0ull, c1B_ = 0ull, d1B_ = 0ull;

        // phase 1: load all quads once; h0 pairs consumed by whh0 + wih1,
        // h1 pairs parked in registers for phase 2.
        u64 h1pA[8], h1pB[8];
#pragma unroll
        for (int q = 0; q < 8; q++) {
            ulonglong2 ta = ((const ulonglong2*)srcA)[q];  // .x=h0 pair, .y=h1 pair
            ulonglong2 tb = ((const ulonglong2*)srcB)[q];
            h1pA[q] = ta.y;
            h1pB[q] = tb.y;
            a0A = fma2(whh0a[q], ta.x, a0A);
            b0A = fma2(whh0b[q], ta.x, b0A);
            a0B = fma2(whh0a[q], tb.x, a0B);
            b0B = fma2(whh0b[q], tb.x, b0B);
            a1A = fma2(wih1a[q], ta.x, a1A);
            b1A = fma2(wih1b[q], ta.x, b1A);
            a1B = fma2(wih1a[q], tb.x, a1B);
            b1B = fma2(wih1b[q], tb.x, b1B);
        }

        // h0 tanh emitted HERE: MUFUs overlap the phase-2 fma issue below.
        float la, ha, lc, hc;
        unpack2(a0A, la, ha);
        unpack2(b0A, lc, hc);
        float h0aA = tanh_mufu(la + ha);
        float h0bA = tanh_mufu(lc + hc);
        unpack2(a0B, la, ha);
        unpack2(b0B, lc, hc);
        float h0aB = tanh_mufu(la + ha);
        float h0bB = tanh_mufu(lc + hc);

        // phase 2: whh1 * h1 on independent accumulators
#pragma unroll
        for (int q = 0; q < 8; q++) {
            c1A_ = fma2(whh1a[q], h1pA[q], c1A_);
            d1A_ = fma2(whh1b[q], h1pA[q], d1A_);
            c1B_ = fma2(whh1a[q], h1pB[q], c1B_);
            d1B_ = fma2(whh1b[q], h1pB[q], d1B_);
        }
        a1A = add2(a1A, c1A_);
        b1A = add2(b1A, d1A_);
        a1B = add2(a1B, c1B_);
        b1B = add2(b1B, d1B_);

        unpack2(a1A, la, ha);
        unpack2(b1A, lc, hc);
        h1aA = tanh_mufu(la + ha);
        h1bA = tanh_mufu(lc + hc);
        unpack2(a1B, la, ha);
        unpack2(b1B, lc, hc);
        h1aB = tanh_mufu(la + ha);
        h1bB = tanh_mufu(lc + hc);
        if (zero_h1) { h1aA = h1bA = h1aB = h1bB = 0.f; }

        ulonglong2 stA, stB;
        stA.x = pack2(h0aA, h0bA);
        stA.y = pack2(h1aA, h1bA);
        stB.x = pack2(h0aB, h0bB);
        stB.y = pack2(h1aB, h1bB);
        ((ulonglong2*)dstA)[k] = stA;
        ((ulonglong2*)dstB)[k] = stB;
    };

    float2 xA = *(const float2*)xbA;
    float2 xB = *(const float2*)xbB;

#pragma unroll 1
    for (int tt = 0; tt < SEQ / 2; tt++) {
        int tn = (2 * tt + 2 < SEQ) ? 2 * tt + 2 : (SEQ - 2);
        float2 xAn = *(const float2*)(xbA + tn);
        float2 xBn = *(const float2*)(xbB + tn);

        substep(r0A, r0B, r1A, r1B, xA.x, xB.x, tt == 0);
        __syncwarp();
        substep(r1A, r1B, r0A, r0B, xA.y, xB.y, false);
        __syncwarp();

        xA = xAn;
        xB = xBn;
    }

    // peel final sub-step: computes h1(SEQ-1) (h0(SEQ) discarded); x value
    // only feeds the discarded h0, any finite value is fine.
    substep(r0A, r0B, r1A, r1B, xA.x, xB.x, false);

    // ---- fc on h1(SEQ-1): partial over own 2 rows, reduce across 8 lanes ----
    const float wfa = Wfc[ra], wfb = Wfc[rb], bf0 = bfc[0];
    float pA = fmaf(wfa, h1aA, wfb * h1bA);
    float pB = fmaf(wfa, h1aB, wfb * h1bB);
    pA += __shfl_down_sync(0xffffffffu, pA, 4, 8);
    pB += __shfl_down_sync(0xffffffffu, pB, 4, 8);
    pA += __shfl_down_sync(0xffffffffu, pA, 2, 8);
    pB += __shfl_down_sync(0xffffffffu, pB, 2, 8);
    pA += __shfl_down_sync(0xffffffffu, pA, 1, 8);
    pB += __shfl_down_sync(0xffffffffu, pB, 1, 8);
    if (k == 0) {
        out[bA] = pA + bf0;
        out[bB] = pB + bf0;
    }
}

extern "C" void kernel_launch(void* const* d_in, const int* in_sizes, int n_in,
                              void* d_out, int out_size)
{
    const float* x    = (const float*)d_in[0];
    const float* Wih0 = (const float*)d_in[1];
    const float* Whh0 = (const float*)d_in[2];
    const float* bih0 = (const float*)d_in[3];
    const float* bhh0 = (const float*)d_in[4];
    const float* Wih1 = (const float*)d_in[5];
    const float* Whh1 = (const float*)d_in[6];
    const float* bih1 = (const float*)d_in[7];
    const float* bhh1 = (const float*)d_in[8];
    const float* Wfc  = (const float*)d_in[9];
    const float* bfc  = (const float*)d_in[10];
    float* out = (float*)d_out;

    rnn2_kernel<<<BATCH / BPB, THREADS>>>(x, Wih0, Whh0, bih0, bhh0,
                                          Wih1, Whh1, bih1, bhh1,
                                          Wfc, bfc, out);
}

// round 13
// speedup vs baseline: 1.2351x; 1.0148x over previous
#include <cuda_runtime.h>

// SimpleRNN: 2-layer tanh RNN, B=8192, S=512, H=16, INPUT=1, fc on last step.
// R11: 16 lanes per batch, 2 batches per warp -> 4096 warps (6.9/SMSP), the
// parallelism the latency model says we were missing. Each thread owns one
// row r of both layers for its batch: 24 fma2 + 8 LDS.128 + 2 MUFU per
// substep. h-state exchange f32 in smem, HROW=48 makes batch-A/B store banks
// disjoint. Layer-1 lagged one step, double-buffered parity, MUFU tanh.

#define BATCH   8192
#define SEQ     512
#define HID     16
#define THREADS 128       // 4 warps; each warp = 2 batches x 16 lanes
#define BPB     8         // batches per block
#define HROW    48        // f32 per batch row: h0[0..15], h1[16..31], pad

typedef unsigned long long u64;

__device__ __forceinline__ u64 fma2(u64 a, u64 b, u64 c) {
    u64 d;
    asm("fma.rn.f32x2 %0, %1, %2, %3;" : "=l"(d) : "l"(a), "l"(b), "l"(c));
    return d;
}
__device__ __forceinline__ u64 add2(u64 a, u64 b) {
    u64 d;
    asm("add.rn.f32x2 %0, %1, %2;" : "=l"(d) : "l"(a), "l"(b));
    return d;
}
__device__ __forceinline__ u64 pack2(float lo, float hi) {
    u64 d;
    asm("mov.b64 %0, {%1, %2};" : "=l"(d) : "f"(lo), "f"(hi));
    return d;
}
__device__ __forceinline__ void unpack2(u64 v, float& lo, float& hi) {
    asm("mov.b64 {%0, %1}, %2;" : "=f"(lo), "=f"(hi) : "l"(v));
}
__device__ __forceinline__ float tanh_mufu(float v) {
    float r;
    asm("tanh.approx.f32 %0, %1;" : "=f"(r) : "f"(v));
    return r;
}

__global__ __launch_bounds__(THREADS)
void rnn2_kernel(const float* __restrict__ x,
                 const float* __restrict__ Wih0, const float* __restrict__ Whh0,
                 const float* __restrict__ bih0, const float* __restrict__ bhh0,
                 const float* __restrict__ Wih1, const float* __restrict__ Whh1,
                 const float* __restrict__ bih1, const float* __restrict__ bhh1,
                 const float* __restrict__ Wfc,  const float* __restrict__ bfc,
                 float* __restrict__ out)
{
    // double-buffered state per batch row: [0..15]=h0, [16..31]=h1, pad to 48
    __shared__ __align__(16) float hbuf[2][BPB][HROW];

    const int tid    = threadIdx.x;
    const int w      = tid >> 5;        // warp 0..3
    const int lane   = tid & 31;
    const int half   = lane >> 4;       // 0 = batch A, 1 = batch B
    const int r      = lane & 15;       // owned hidden row
    const int rowIdx = 2 * w + half;    // smem row within block
    const int b      = blockIdx.x * BPB + rowIdx;

    // ---- this thread's weight rows, packed f32x2 along j ----
    u64 whh0[8], wih1[8], whh1[8];
#pragma unroll
    for (int j = 0; j < 8; j++) {
        whh0[j] = *(const u64*)(Whh0 + r * HID + 2 * j);
        wih1[j] = *(const u64*)(Wih1 + r * HID + 2 * j);
        whh1[j] = *(const u64*)(Whh1 + r * HID + 2 * j);
    }
    const float wi0 = Wih0[r];
    const float c0  = bih0[r] + bhh0[r];
    const float c1  = bih1[r] + bhh1[r];

    float* r0 = &hbuf[0][rowIdx][0];
    float* r1 = &hbuf[1][rowIdx][0];

    // zero parity-0 state
    r0[r]      = 0.f;
    r0[16 + r] = 0.f;
    __syncwarp();

    const float* xb = x + (size_t)b * SEQ;
    float h1r = 0.f;

    // one substep at global time t: reads src {h0(t-1), h1(t-2)}, computes
    // h0(t) and h1(t-1), stores to dst. zero_h1 forces h1(-1)=0 at t=0.
    auto substep = [&](const float* src, float* dst, float xv, bool zero_h1) {
        u64 a0 = pack2(fmaf(wi0, xv, c0), 0.f);
        u64 a1 = pack2(c1, 0.f);
        u64 b1 = 0ull;   // bits of (0.f, 0.f)
        const ulonglong2* h0q = (const ulonglong2*)src;
        const ulonglong2* h1q = (const ulonglong2*)(src + 16);
#pragma unroll
        for (int q = 0; q < 4; q++) {
            ulonglong2 t = h0q[q];          // h0 pairs 2q, 2q+1
            a0 = fma2(whh0[2 * q],     t.x, a0);
            a1 = fma2(wih1[2 * q],     t.x, a1);
            a0 = fma2(whh0[2 * q + 1], t.y, a0);
            a1 = fma2(wih1[2 * q + 1], t.y, a1);
        }
#pragma unroll
        for (int q = 0; q < 4; q++) {
            ulonglong2 t = h1q[q];          // h1 pairs 2q, 2q+1
            b1 = fma2(whh1[2 * q],     t.x, b1);
            b1 = fma2(whh1[2 * q + 1], t.y, b1);
        }
        float lo, hi;
        unpack2(a0, lo, hi);
        float h0r = tanh_mufu(lo + hi);
        a1 = add2(a1, b1);
        unpack2(a1, lo, hi);
        h1r = tanh_mufu(lo + hi);
        if (zero_h1) h1r = 0.f;
        dst[r]      = h0r;   // banks disjoint across halves (HROW=48)
        dst[16 + r] = h1r;
    };

    float2 xc = *(const float2*)xb;

#pragma unroll 1
    for (int tt = 0; tt < SEQ / 2; tt++) {
        int tn = (2 * tt + 2 < SEQ) ? 2 * tt + 2 : (SEQ - 2);
        float2 xn = *(const float2*)(xb + tn);

        substep(r0, r1, xc.x, tt == 0);
        __syncwarp();
        substep(r1, r0, xc.y, false);
        __syncwarp();

        xc = xn;
    }

    // peel: after the loop r0 holds {h0(511), h1(510)}; compute h1(511).
    {
        u64 a1 = pack2(c1, 0.f);
        u64 b1 = 0ull;
        const ulonglong2* h0q = (const ulonglong2*)r0;
        const ulonglong2* h1q = (const ulonglong2*)(r0 + 16);
#pragma unroll
        for (int q = 0; q < 4; q++) {
            ulonglong2 t = h0q[q];
            a1 = fma2(wih1[2 * q],     t.x, a1);
            a1 = fma2(wih1[2 * q + 1], t.y, a1);
        }
#pragma unroll
        for (int q = 0; q < 4; q++) {
            ulonglong2 t = h1q[q];
            b1 = fma2(whh1[2 * q],     t.x, b1);
            b1 = fma2(whh1[2 * q + 1], t.y, b1);
        }
        a1 = add2(a1, b1);
        float lo, hi;
        unpack2(a1, lo, hi);
        h1r = tanh_mufu(lo + hi);
    }

    // ---- fc: reduce Wfc[r]*h1r across the 16 lanes of each half ----
    float p = Wfc[r] * h1r;
    p += __shfl_xor_sync(0xffffffffu, p, 8, 16);
    p += __shfl_xor_sync(0xffffffffu, p, 4, 16);
    p += __shfl_xor_sync(0xffffffffu, p, 2, 16);
    p += __shfl_xor_sync(0xffffffffu, p, 1, 16);
    if (r == 0) out[b] = p + bfc[0];
}

extern "C" void kernel_launch(void* const* d_in, const int* in_sizes, int n_in,
                              void* d_out, int out_size)
{
    const float* x    = (const float*)d_in[0];
    const float* Wih0 = (const float*)d_in[1];
    const float* Whh0 = (const float*)d_in[2];
    const float* bih0 = (const float*)d_in[3];
    const float* bhh0 = (const float*)d_in[4];
    const float* Wih1 = (const float*)d_in[5];
    const float* Whh1 = (const float*)d_in[6];
    const float* bih1 = (const float*)d_in[7];
    const float* bhh1 = (const float*)d_in[8];
    const float* Wfc  = (const float*)d_in[9];
    const float* bfc  = (const float*)d_in[10];
    float* out = (float*)d_out;

    rnn2_kernel<<<BATCH / BPB, THREADS>>>(x, Wih0, Whh0, bih0, bhh0,
                                          Wih1, Whh1, bih1, bhh1,
                                          Wfc, bfc, out);
}

// round 14
// speedup vs baseline: 3.4455x; 2.7896x over previous
#include <cuda_runtime.h>
#include <cuda_fp16.h>

// SimpleRNN: 2-layer tanh RNN, B=8192, S=512, H=16, INPUT=1, fc on last step.
// R13: tensor-core recurrence. Each warp owns 16 batches; the 16x16 matvecs
// are mma.sync.m16n8k16 (f16 in, f32 accum). The m16n8 D fragment layout is
// per-lane identical to the m16k16 A fragment layout, so h(t) -> h(t+1)
// needs only tanh + float->half2 packs in registers: no smem, no shuffles,
// no syncs. Weights use an fp16 hi/lo split (exact to ~2^-23), so the only
// quantization is fp16 h (empirically 4e-4 final in R6). Layer-1 lagged one
// step. 4 warps/block so warps land on distinct SMSPs; grid 128 = one wave.

#define SEQ     512
#define HID     16
#define WPB     4
#define THREADS (WPB * 32)
#define BATCH   8192

typedef unsigned int u32;

__device__ __forceinline__ float tanh_mufu(float v) {
    float r;
    asm("tanh.approx.f32 %0, %1;" : "=f"(r) : "f"(v));
    return r;
}
__device__ __forceinline__ u32 pack_h2(float a, float b) {
    __half2 h = __floats2half2_rn(a, b);
    return *reinterpret_cast<u32*>(&h);
}
__device__ __forceinline__ u32 pack_halves(__half a, __half b) {
    __half2 h = __halves2half2(a, b);
    return *reinterpret_cast<u32*>(&h);
}
// D += A @ B  (m16n8k16, f16 inputs, f32 accumulate)
__device__ __forceinline__ void mma16816(float& d0, float& d1, float& d2, float& d3,
                                         u32 a0, u32 a1, u32 a2, u32 a3,
                                         u32 b0, u32 b1) {
    asm("mma.sync.aligned.m16n8k16.row.col.f32.f16.f16.f32 "
        "{%0,%1,%2,%3}, {%4,%5,%6,%7}, {%8,%9}, {%0,%1,%2,%3};"
        : "+f"(d0), "+f"(d1), "+f"(d2), "+f"(d3)
        : "r"(a0), "r"(a1), "r"(a2), "r"(a3), "r"(b0), "r"(b1));
}

__global__ __launch_bounds__(THREADS)
void rnn2_kernel(const float* __restrict__ x,
                 const float* __restrict__ Wih0, const float* __restrict__ Whh0,
                 const float* __restrict__ bih0, const float* __restrict__ bhh0,
                 const float* __restrict__ Wih1, const float* __restrict__ Whh1,
                 const float* __restrict__ bih1, const float* __restrict__ bhh1,
                 const float* __restrict__ Wfc,  const float* __restrict__ bfc,
                 float* __restrict__ out)
{
    const int w    = threadIdx.x >> 5;
    const int lane = threadIdx.x & 31;
    const int g    = lane >> 2;      // group 0..7 (row / n index)
    const int tg   = lane & 3;       // thread-in-group (col pairs)
    const int base = (blockIdx.x * WPB + w) * 16;   // first batch of this warp

    // ---- B fragments: B[k][n] = W[n][k] (col-major k16n8), hi/lo split ----
    // [tau][reg]: tau = n-tile (n = g+8*tau); reg0 = k rows 2tg,2tg+1; reg1 = +8.
    u32 Bh0[2][2], Bl0[2][2];   // Whh0
    u32 Bh1[2][2], Bl1[2][2];   // Wih1
    u32 Bh2[2][2], Bl2[2][2];   // Whh1
    {
        const float* Ws[3] = { Whh0, Wih1, Whh1 };
        for (int m = 0; m < 3; m++) {
            for (int tau = 0; tau < 2; tau++) {
                int n = g + 8 * tau;
                const float* row = Ws[m] + n * HID;
                float w0 = row[2 * tg],     w1 = row[2 * tg + 1];
                float w2 = row[2 * tg + 8], w3 = row[2 * tg + 9];
                __half h0 = __float2half_rn(w0), h1 = __float2half_rn(w1);
                __half h2 = __float2half_rn(w2), h3 = __float2half_rn(w3);
                __half l0 = __float2half_rn(w0 - __half2float(h0));
                __half l1 = __float2half_rn(w1 - __half2float(h1));
                __half l2 = __float2half_rn(w2 - __half2float(h2));
                __half l3 = __float2half_rn(w3 - __half2float(h3));
                u32 bh0 = pack_halves(h0, h1), bh1 = pack_halves(h2, h3);
                u32 bl0 = pack_halves(l0, l1), bl1 = pack_halves(l2, l3);
                if (m == 0) { Bh0[tau][0] = bh0; Bh0[tau][1] = bh1; Bl0[tau][0] = bl0; Bl0[tau][1] = bl1; }
                if (m == 1) { Bh1[tau][0] = bh0; Bh1[tau][1] = bh1; Bl1[tau][0] = bl0; Bl1[tau][1] = bl1; }
                if (m == 2) { Bh2[tau][0] = bh0; Bh2[tau][1] = bh1; Bl2[tau][0] = bl0; Bl2[tau][1] = bl1; }
            }
        }
    }

    // per-lane column constants, index j -> col {2tg, 2tg+1, 2tg+8, 2tg+9}
    float wi0c[4], c0c[4], c1c[4], wfcc[4];
    {
        int cols[4] = { 2 * tg, 2 * tg + 1, 2 * tg + 8, 2 * tg + 9 };
#pragma unroll
        for (int j = 0; j < 4; j++) {
            int c = cols[j];
            wi0c[j] = Wih0[c];
            c0c[j]  = bih0[c] + bhh0[c];
            c1c[j]  = bih1[c] + bhh1[c];
            wfcc[j] = Wfc[c];
        }
    }

    const float* xg_ptr  = x + (size_t)(base + g) * SEQ;
    const float* xg8_ptr = x + (size_t)(base + g + 8) * SEQ;

    // A fragments (fp16) for h0(t-1) and h1(t-2); start at zero state.
    u32 A0[4] = {0u, 0u, 0u, 0u};
    u32 A1[4] = {0u, 0u, 0u, 0u};

    // one substep at time t: consumes A0=h0(t-1), A1=h1(t-2) and x(t);
    // produces A0=h0(t), A1=h1(t-1) in fragment layout.
    auto substep = [&](float xg, float xg8, bool zero_h1) {
        float e[8], f[8];
        // layer0 init: wi0*x + bias  (rows g / g+8 map to regs {0,1}/{2,3})
        e[0] = fmaf(wi0c[0], xg,  c0c[0]);
        e[1] = fmaf(wi0c[1], xg,  c0c[1]);
        e[2] = fmaf(wi0c[0], xg8, c0c[0]);
        e[3] = fmaf(wi0c[1], xg8, c0c[1]);
        e[4] = fmaf(wi0c[2], xg,  c0c[2]);
        e[5] = fmaf(wi0c[3], xg,  c0c[3]);
        e[6] = fmaf(wi0c[2], xg8, c0c[2]);
        e[7] = fmaf(wi0c[3], xg8, c0c[3]);
        // layer1 init: bias only
        f[0] = c1c[0]; f[1] = c1c[1]; f[2] = c1c[0]; f[3] = c1c[1];
        f[4] = c1c[2]; f[5] = c1c[3]; f[6] = c1c[2]; f[7] = c1c[3];

        // pre0 = h0(t-1) @ Whh0^T  (hi + lo)
        mma16816(e[0], e[1], e[2], e[3], A0[0], A0[1], A0[2], A0[3], Bh0[0][0], Bh0[0][1]);
        mma16816(e[0], e[1], e[2], e[3], A0[0], A0[1], A0[2], A0[3], Bl0[0][0], Bl0[0][1]);
        mma16816(e[4], e[5], e[6], e[7], A0[0], A0[1], A0[2], A0[3], Bh0[1][0], Bh0[1][1]);
        mma16816(e[4], e[5], e[6], e[7], A0[0], A0[1], A0[2], A0[3], Bl0[1][0], Bl0[1][1]);
        // pre1 = h0(t-1) @ Wih1^T + h1(t-2) @ Whh1^T  (hi + lo each)
        mma16816(f[0], f[1], f[2], f[3], A0[0], A0[1], A0[2], A0[3], Bh1[0][0], Bh1[0][1]);
        mma16816(f[0], f[1], f[2], f[3], A0[0], A0[1], A0[2], A0[3], Bl1[0][0], Bl1[0][1]);
        mma16816(f[4], f[5], f[6], f[7], A0[0], A0[1], A0[2], A0[3], Bh1[1][0], Bh1[1][1]);
        mma16816(f[4], f[5], f[6], f[7], A0[0], A0[1], A0[2], A0[3], Bl1[1][0], Bl1[1][1]);
        mma16816(f[0], f[1], f[2], f[3], A1[0], A1[1], A1[2], A1[3], Bh2[0][0], Bh2[0][1]);
        mma16816(f[0], f[1], f[2], f[3], A1[0], A1[1], A1[2], A1[3], Bl2[0][0], Bl2[0][1]);
        mma16816(f[4], f[5], f[6], f[7], A1[0], A1[1], A1[2], A1[3], Bh2[1][0], Bh2[1][1]);
        mma16816(f[4], f[5], f[6], f[7], A1[0], A1[1], A1[2], A1[3], Bl2[1][0], Bl2[1][1]);

        // activations + repack: D(m16n8) layout == A(m16k16) layout per lane
        A0[0] = pack_h2(tanh_mufu(e[0]), tanh_mufu(e[1]));
        A0[1] = pack_h2(tanh_mufu(e[2]), tanh_mufu(e[3]));
        A0[2] = pack_h2(tanh_mufu(e[4]), tanh_mufu(e[5]));
        A0[3] = pack_h2(tanh_mufu(e[6]), tanh_mufu(e[7]));
        if (zero_h1) {
            A1[0] = A1[1] = A1[2] = A1[3] = 0u;   // h1(-1) = 0
        } else {
            A1[0] = pack_h2(tanh_mufu(f[0]), tanh_mufu(f[1]));
            A1[1] = pack_h2(tanh_mufu(f[2]), tanh_mufu(f[3]));
            A1[2] = pack_h2(tanh_mufu(f[4]), tanh_mufu(f[5]));
            A1[3] = pack_h2(tanh_mufu(f[6]), tanh_mufu(f[7]));
        }
    };

    float4 cg  = *(const float4*)xg_ptr;
    float4 cg8 = *(const float4*)xg8_ptr;

#pragma unroll 1
    for (int tc = 0; tc < SEQ; tc += 4) {
        int tn = (tc + 4 < SEQ) ? tc + 4 : (SEQ - 4);
        float4 ng  = *(const float4*)(xg_ptr + tn);
        float4 ng8 = *(const float4*)(xg8_ptr + tn);

        substep(cg.x, cg8.x, tc == 0);
        substep(cg.y, cg8.y, false);
        substep(cg.z, cg8.z, false);
        substep(cg.w, cg8.w, false);

        cg = ng; cg8 = ng8;
    }

    // ---- epilogue: h1(511) = tanh(Wih1 h0(511) + Whh1 h1(510) + c1) ----
    float f[8];
    f[0] = c1c[0]; f[1] = c1c[1]; f[2] = c1c[0]; f[3] = c1c[1];
    f[4] = c1c[2]; f[5] = c1c[3]; f[6] = c1c[2]; f[7] = c1c[3];
    mma16816(f[0], f[1], f[2], f[3], A0[0], A0[1], A0[2], A0[3], Bh1[0][0], Bh1[0][1]);
    mma16816(f[0], f[1], f[2], f[3], A0[0], A0[1], A0[2], A0[3], Bl1[0][0], Bl1[0][1]);
    mma16816(f[4], f[5], f[6], f[7], A0[0], A0[1], A0[2], A0[3], Bh1[1][0], Bh1[1][1]);
    mma16816(f[4], f[5], f[6], f[7], A0[0], A0[1], A0[2], A0[3], Bl1[1][0], Bl1[1][1]);
    mma16816(f[0], f[1], f[2], f[3], A1[0], A1[1], A1[2], A1[3], Bh2[0][0], Bh2[0][1]);
    mma16816(f[0], f[1], f[2], f[3], A1[0], A1[1], A1[2], A1[3], Bl2[0][0], Bl2[0][1]);
    mma16816(f[4], f[5], f[6], f[7], A1[0], A1[1], A1[2], A1[3], Bh2[1][0], Bh2[1][1]);
    mma16816(f[4], f[5], f[6], f[7], A1[0], A1[1], A1[2], A1[3], Bl2[1][0], Bl2[1][1]);

    // fc over n: row g uses regs {0,1} (cols 2tg,2tg+1) and tile1 {4,5}
    // (cols 2tg+8,2tg+9); row g+8 uses {2,3} and {6,7}.
    float pg  = wfcc[0] * tanh_mufu(f[0]) + wfcc[1] * tanh_mufu(f[1])
              + wfcc[2] * tanh_mufu(f[4]) + wfcc[3] * tanh_mufu(f[5]);
    float pg8 = wfcc[0] * tanh_mufu(f[2]) + wfcc[1] * tanh_mufu(f[3])
              + wfcc[2] * tanh_mufu(f[6]) + wfcc[3] * tanh_mufu(f[7]);
    pg  += __shfl_xor_sync(0xffffffffu, pg, 1, 4);
    pg8 += __shfl_xor_sync(0xffffffffu, pg8, 1, 4);
    pg  += __shfl_xor_sync(0xffffffffu, pg, 2, 4);
    pg8 += __shfl_xor_sync(0xffffffffu, pg8, 2, 4);
    if (tg == 0) {
        float b0 = bfc[0];
        out[base + g]     = pg + b0;
        out[base + g + 8] = pg8 + b0;
    }
}

extern "C" void kernel_launch(void* const* d_in, const int* in_sizes, int n_in,
                              void* d_out, int out_size)
{
    const float* x    = (const float*)d_in[0];
    const float* Wih0 = (const float*)d_in[1];
    const float* Whh0 = (const float*)d_in[2];
    const float* bih0 = (const float*)d_in[3];
    const float* bhh0 = (const float*)d_in[4];
    const float* Wih1 = (const float*)d_in[5];
    const float* Whh1 = (const float*)d_in[6];
    const float* bih1 = (const float*)d_in[7];
    const float* bhh1 = (const float*)d_in[8];
    const float* Wfc  = (const float*)d_in[9];
    const float* bfc  = (const float*)d_in[10];
    float* out = (float*)d_out;

    rnn2_kernel<<<BATCH / (WPB * 16), THREADS>>>(x, Wih0, Whh0, bih0, bhh0,
                                                 Wih1, Whh1, bih1, bhh1,
                                                 Wfc, bfc, out);
}